// round 8
// baseline (speedup 1.0000x reference)
#include <cuda_runtime.h>
#include <cuda_bf16.h>
#include <cstdint>

#define N_NODES 100000
#define N_EDGES 600000
#define D_IN    128
#define D_OUT   96
#define N_REL   4

#define N_TILES  782                 // ceil(100000/128)

#define ROW_BYTES 272                // 128 bf16 (256B) + 16B pad -> conflict-free ldmatrix
#define A_IMG_BYTES (128 * ROW_BYTES)      // 34816
#define B1_ROWS 128
#define B2_ROWS 96
#define B1_IMG_BYTES (B1_ROWS * ROW_BYTES) // 34816
#define B2_IMG_BYTES (B2_ROWS * ROW_BYTES) // 26112

#define SCAN_BLK   1024
#define N_SCANBLKS 98                // ceil(100000/1024)

// ---------------- scratch (static device globals; no allocs allowed) --------
__device__ __align__(16) float g_out1[(size_t)N_NODES * D_IN];          // 51.2 MB
__device__ int      g_cnt[N_NODES * N_REL];
__device__ int      g_cursor[N_NODES * N_REL];
__device__ int      g_base[N_NODES];
__device__ int      g_blocksum[N_SCANBLKS];
__device__ int      g_blockoff[N_SCANBLKS];
__device__ uint32_t g_csr[N_EDGES];

// weight images (bf16 hi/lo, padded rows). B2 rows 96 only.
__device__ uint4 g_B1hi[5 * (B1_IMG_BYTES / 16)];
__device__ uint4 g_B1lo[5 * (B1_IMG_BYTES / 16)];
__device__ uint4 g_B2hi[5 * (B2_IMG_BYTES / 16)];
__device__ uint4 g_B2lo[5 * (B2_IMG_BYTES / 16)];

// ---------------- helpers ----------------------------------------------------
__device__ __forceinline__ uint32_t smem_u32(const void* p) {
    uint32_t a;
    asm("{ .reg .u64 t; cvta.to.shared.u64 t, %1; cvt.u32.u64 %0, t; }" : "=r"(a) : "l"(p));
    return a;
}

#define LDSM4(r, addr)                                                        \
    asm volatile("ldmatrix.sync.aligned.m8n8.x4.shared.b16 {%0,%1,%2,%3}, [%4];" \
                 : "=r"((r)[0]), "=r"((r)[1]), "=r"((r)[2]), "=r"((r)[3])     \
                 : "r"(addr))

#define MMA16816(d, a, b0, b1)                                                \
    asm volatile("mma.sync.aligned.m16n8k16.row.col.f32.bf16.bf16.f32 "       \
                 "{%0,%1,%2,%3},{%4,%5,%6,%7},{%8,%9},{%0,%1,%2,%3};"         \
                 : "+f"((d)[0]), "+f"((d)[1]), "+f"((d)[2]), "+f"((d)[3])     \
                 : "r"((a)[0]), "r"((a)[1]), "r"((a)[2]), "r"((a)[3]),        \
                   "r"(b0), "r"(b1))

__device__ __forceinline__ uint32_t pack_bf16x2(__nv_bfloat16 a, __nv_bfloat16 b) {
    uint32_t r;
    asm("mov.b32 %0, {%1, %2};" : "=r"(r)
        : "h"(*(unsigned short*)&a), "h"(*(unsigned short*)&b));
    return r;
}

// split float4 -> hi/lo bf16x2 pairs and store 8B each
__device__ __forceinline__ void split_store8(char* hi_p, char* lo_p, float4 v) {
    __nv_bfloat16 h0 = __float2bfloat16(v.x), h1 = __float2bfloat16(v.y);
    __nv_bfloat16 h2 = __float2bfloat16(v.z), h3 = __float2bfloat16(v.w);
    __nv_bfloat16 l0 = __float2bfloat16(v.x - __bfloat162float(h0));
    __nv_bfloat16 l1 = __float2bfloat16(v.y - __bfloat162float(h1));
    __nv_bfloat16 l2 = __float2bfloat16(v.z - __bfloat162float(h2));
    __nv_bfloat16 l3 = __float2bfloat16(v.w - __bfloat162float(h3));
    uint2 h = make_uint2(pack_bf16x2(h0, h1), pack_bf16x2(h2, h3));
    uint2 l = make_uint2(pack_bf16x2(l0, l1), pack_bf16x2(l2, l3));
    *(uint2*)hi_p = h;
    *(uint2*)lo_p = l;
}

// ---------------- CSR build --------------------------------------------------
__global__ void zero_cnt_kernel() {
    int i = blockIdx.x * blockDim.x + threadIdx.x;
    if (i < N_NODES * N_REL) { g_cnt[i] = 0; g_cursor[i] = 0; }
}
__global__ void count_kernel(const int* __restrict__ ei, const int* __restrict__ et) {
    int e = blockIdx.x * blockDim.x + threadIdx.x;
    if (e < N_EDGES) atomicAdd(&g_cnt[ei[N_EDGES + e] * N_REL + et[e]], 1);
}
__global__ void scan1_kernel() {
    __shared__ int s[SCAN_BLK];
    int tid = threadIdx.x;
    int d = blockIdx.x * SCAN_BLK + tid;
    int deg = 0;
    if (d < N_NODES)
        deg = g_cnt[d*4] + g_cnt[d*4+1] + g_cnt[d*4+2] + g_cnt[d*4+3];
    s[tid] = deg;
    __syncthreads();
    for (int off = 1; off < SCAN_BLK; off <<= 1) {
        int v = (tid >= off) ? s[tid - off] : 0;
        __syncthreads();
        s[tid] += v;
        __syncthreads();
    }
    if (d < N_NODES) g_base[d] = s[tid] - deg;          // exclusive (local)
    if (tid == SCAN_BLK - 1) g_blocksum[blockIdx.x] = s[tid];
}
__global__ void scan2_kernel() {
    __shared__ int s[128];
    int tid = threadIdx.x;
    int v = (tid < N_SCANBLKS) ? g_blocksum[tid] : 0;
    s[tid] = v;
    __syncthreads();
    for (int off = 1; off < 128; off <<= 1) {
        int u = (tid >= off) ? s[tid - off] : 0;
        __syncthreads();
        s[tid] += u;
        __syncthreads();
    }
    if (tid < N_SCANBLKS) g_blockoff[tid] = s[tid] - v; // exclusive
}
__global__ void scanfix_kernel() {
    int d = blockIdx.x * SCAN_BLK + threadIdx.x;
    if (d < N_NODES) g_base[d] += g_blockoff[blockIdx.x];
}
__global__ void reorder_kernel(const int* __restrict__ ei, const int* __restrict__ et) {
    int e = blockIdx.x * blockDim.x + threadIdx.x;
    if (e >= N_EDGES) return;
    int src = ei[e];
    int dst = ei[N_EDGES + e];
    int t   = et[e];
    int pos = atomicAdd(&g_cursor[dst * N_REL + t], 1);
    int sub = 0;
#pragma unroll
    for (int j = 0; j < N_REL - 1; j++) if (j < t) sub += g_cnt[dst * N_REL + j];
    g_csr[g_base[dst] + sub + pos] = (uint32_t)src;
}

// ---------------- weight image prep ------------------------------------------
__global__ void prep_w1(const float* __restrict__ W, const float* __restrict__ root) {
    int e = blockIdx.x * blockDim.x + threadIdx.x;
    if (e >= 5 * 128 * 128) return;
    int batch = e / 16384, r = e % 16384;
    int k = r / 128, n = r % 128;
    float v = (batch < 4) ? W[(size_t)batch * 16384 + k * 128 + n] : root[k * 128 + n];
    __nv_bfloat16 hi = __float2bfloat16(v);
    __nv_bfloat16 lo = __float2bfloat16(v - __bfloat162float(hi));
    size_t off = (size_t)batch * B1_IMG_BYTES + (size_t)n * ROW_BYTES + (size_t)k * 2;
    *(__nv_bfloat16*)((char*)g_B1hi + off) = hi;
    *(__nv_bfloat16*)((char*)g_B1lo + off) = lo;
}
__global__ void prep_w2(const float* __restrict__ W, const float* __restrict__ root) {
    int e = blockIdx.x * blockDim.x + threadIdx.x;
    if (e >= 5 * 128 * 96) return;
    int batch = e / 12288, r = e % 12288;
    int k = r / 96, n = r % 96;
    float v = (batch < 4) ? W[(size_t)batch * 12288 + k * 96 + n] : root[k * 96 + n];
    __nv_bfloat16 hi = __float2bfloat16(v);
    __nv_bfloat16 lo = __float2bfloat16(v - __bfloat162float(hi));
    size_t off = (size_t)batch * B2_IMG_BYTES + (size_t)n * ROW_BYTES + (size_t)k * 2;
    *(__nv_bfloat16*)((char*)g_B2hi + off) = hi;
    *(__nv_bfloat16*)((char*)g_B2lo + off) = lo;
}

// ---------------- fused aggregate+GEMM ---------------------------------------
// One CTA per 128-dst tile. For batch r<4: stage A = Y_r (CSR gather-aggregate
// of x[src] rows, fp32 regs, normalized, bf16 hi/lo split). Batch 4: A = x[d].
// MMA accumulates ALL batches into one fp32 accumulator; epilogue writes the
// complete layer output (agg + x@root + b). No scatter, no H buffers.
template <int DOUT, int SRC>   // SRC 0: feats = x (ext); 1: feats = relu(g_out1)
__global__ __launch_bounds__(512, 1)
void gemm_fused(const float* __restrict__ xext, const float* __restrict__ bias,
                float* __restrict__ out_ext)
{
    constexpr int B_IMG = (DOUT == 128) ? B1_IMG_BYTES : B2_IMG_BYTES;
    constexpr int B_U4  = B_IMG / 16;
    extern __shared__ char smem[];
    char* sAhi = smem;
    char* sAlo = smem + A_IMG_BYTES;
    char* sBhi = smem + 2 * A_IMG_BYTES;
    char* sBlo = smem + 2 * A_IMG_BYTES + B_IMG;

    int tid = threadIdx.x;
    int wid = tid >> 5, lane = tid & 31;
    int tile = blockIdx.x;

    const float* feats = (SRC == 0) ? xext : g_out1;
    float* Obuf = (DOUT == 128) ? g_out1 : out_ext;

    int warp_m = (wid & 3) * 32;
    int warp_n = (wid >> 2) * 32;
    bool active = (warp_n < DOUT);

    uint32_t sb = smem_u32(smem);
    uint32_t aoff = (uint32_t)(warp_m + (lane & 15)) * ROW_BYTES + ((lane >> 4) & 1) * 16;
    uint32_t boff = (uint32_t)(warp_n + (lane & 7) + ((lane >> 4) & 1) * 8) * ROW_BYTES
                  + ((lane >> 3) & 1) * 16;

    float acc[2][4][4];
#pragma unroll
    for (int i = 0; i < 2; i++)
#pragma unroll
        for (int j = 0; j < 4; j++)
#pragma unroll
            for (int q = 0; q < 4; q++) acc[i][j][q] = 0.f;

#pragma unroll 1
    for (int batch = 0; batch < 5; batch++) {
        if (batch > 0) __syncthreads();   // prior MMA done reading smem

        // ---- stage A: warp w owns rows w*8..w*8+7 --------------------------
#pragma unroll 1
        for (int i = 0; i < 8; i++) {
            int dl = wid * 8 + i;
            int d  = tile * 128 + dl;
            float4 a = make_float4(0.f, 0.f, 0.f, 0.f);
            if (d < N_NODES) {
                if (batch < 4) {
                    // relation aggregate via CSR
                    int c0 = g_cnt[d*4], c1 = g_cnt[d*4+1], c2 = g_cnt[d*4+2], c3 = g_cnt[d*4+3];
                    int sub = (batch > 0 ? c0 : 0) + (batch > 1 ? c1 : 0) + (batch > 2 ? c2 : 0);
                    int c = (batch == 0) ? c0 : (batch == 1) ? c1 : (batch == 2) ? c2 : c3;
                    const uint32_t* ep = g_csr + g_base[d] + sub;
                    float4 a2 = make_float4(0.f, 0.f, 0.f, 0.f);
                    int e = 0;
                    for (; e + 1 < c; e += 2) {
                        int s0 = ep[e], s1 = ep[e + 1];
                        float4 v0 = ((const float4*)(feats + (size_t)s0 * 128))[lane];
                        float4 v1 = ((const float4*)(feats + (size_t)s1 * 128))[lane];
                        if (SRC == 1) {
                            v0.x = fmaxf(v0.x, 0.f); v0.y = fmaxf(v0.y, 0.f);
                            v0.z = fmaxf(v0.z, 0.f); v0.w = fmaxf(v0.w, 0.f);
                            v1.x = fmaxf(v1.x, 0.f); v1.y = fmaxf(v1.y, 0.f);
                            v1.z = fmaxf(v1.z, 0.f); v1.w = fmaxf(v1.w, 0.f);
                        }
                        a.x += v0.x; a.y += v0.y; a.z += v0.z; a.w += v0.w;
                        a2.x += v1.x; a2.y += v1.y; a2.z += v1.z; a2.w += v1.w;
                    }
                    if (e < c) {
                        int s0 = ep[e];
                        float4 v0 = ((const float4*)(feats + (size_t)s0 * 128))[lane];
                        if (SRC == 1) {
                            v0.x = fmaxf(v0.x, 0.f); v0.y = fmaxf(v0.y, 0.f);
                            v0.z = fmaxf(v0.z, 0.f); v0.w = fmaxf(v0.w, 0.f);
                        }
                        a.x += v0.x; a.y += v0.y; a.z += v0.z; a.w += v0.w;
                    }
                    float nm = 1.f / (float)(c > 1 ? c : 1);
                    a.x = (a.x + a2.x) * nm; a.y = (a.y + a2.y) * nm;
                    a.z = (a.z + a2.z) * nm; a.w = (a.w + a2.w) * nm;
                } else {
                    // root: own features
                    a = ((const float4*)(feats + (size_t)d * 128))[lane];
                    if (SRC == 1) {
                        a.x = fmaxf(a.x, 0.f); a.y = fmaxf(a.y, 0.f);
                        a.z = fmaxf(a.z, 0.f); a.w = fmaxf(a.w, 0.f);
                    }
                }
            }
            split_store8(sAhi + (size_t)dl * ROW_BYTES + lane * 8,
                         sAlo + (size_t)dl * ROW_BYTES + lane * 8, a);
        }

        // ---- stage B (L2-resident weight images) ---------------------------
        {
            const uint4* bhi = (DOUT == 128 ? g_B1hi : g_B2hi) + (size_t)batch * B_U4;
            const uint4* blo = (DOUT == 128 ? g_B1lo : g_B2lo) + (size_t)batch * B_U4;
            uint4* s2 = (uint4*)sBhi;
            uint4* s3 = (uint4*)sBlo;
            for (int i = tid; i < B_U4; i += 512) { s2[i] = bhi[i]; s3[i] = blo[i]; }
        }
        __syncthreads();

        // ---- MMA: accumulate this batch into persistent acc ----------------
        if (active) {
            uint32_t aA[2][2], bA[2][2];
#pragma unroll
            for (int s = 0; s < 2; s++) {
#pragma unroll
                for (int i = 0; i < 2; i++)
                    aA[s][i] = sb + s * A_IMG_BYTES + aoff + i * 16 * ROW_BYTES;
#pragma unroll
                for (int jj = 0; jj < 2; jj++)
                    bA[s][jj] = sb + 2 * A_IMG_BYTES + s * B_IMG + boff + jj * 16 * ROW_BYTES;
            }
#pragma unroll
            for (int kk = 0; kk < 8; kk++) {
                uint32_t ah[2][4], al[2][4], bh[2][4], bl[2][4];
#pragma unroll
                for (int i = 0; i < 2; i++) {
                    LDSM4(ah[i], aA[0][i]);
                    LDSM4(al[i], aA[1][i]);
                    aA[0][i] += 32; aA[1][i] += 32;
                }
#pragma unroll
                for (int jj = 0; jj < 2; jj++) {
                    LDSM4(bh[jj], bA[0][jj]);
                    LDSM4(bl[jj], bA[1][jj]);
                    bA[0][jj] += 32; bA[1][jj] += 32;
                }
#pragma unroll
                for (int i = 0; i < 2; i++) {
#pragma unroll
                    for (int j = 0; j < 4; j++) {
                        int jj = j >> 1, q = (j & 1) * 2;
                        MMA16816(acc[i][j], ah[i], bh[jj][q], bh[jj][q + 1]);
                        MMA16816(acc[i][j], ah[i], bl[jj][q], bl[jj][q + 1]);
                        MMA16816(acc[i][j], al[i], bh[jj][q], bh[jj][q + 1]);
                    }
                }
            }
        }
    }

    // ---- epilogue: complete layer output = agg + root + bias ---------------
    if (active) {
#pragma unroll
        for (int i = 0; i < 2; i++) {
            int row0 = tile * 128 + warp_m + i * 16 + (lane >> 2);
#pragma unroll
            for (int j = 0; j < 4; j++) {
                int col = warp_n + j * 8 + (lane & 3) * 2;
                if (col >= DOUT) continue;
                float b0 = bias[col], b1 = bias[col + 1];
                float2 v0 = make_float2(acc[i][j][0] + b0, acc[i][j][1] + b1);
                float2 v1 = make_float2(acc[i][j][2] + b0, acc[i][j][3] + b1);
                if (row0 < N_NODES)
                    *(float2*)(Obuf + (size_t)row0 * DOUT + col) = v0;
                if (row0 + 8 < N_NODES)
                    *(float2*)(Obuf + (size_t)(row0 + 8) * DOUT + col) = v1;
            }
        }
    }
}

// ---------------- launch -----------------------------------------------------
#define SMEM1 (2 * A_IMG_BYTES + 2 * B1_IMG_BYTES)   // 139264
#define SMEM2 (2 * A_IMG_BYTES + 2 * B2_IMG_BYTES)   // 121856

extern "C" void kernel_launch(void* const* d_in, const int* in_sizes, int n_in,
                              void* d_out, int out_size)
{
    const float* x     = (const float*)d_in[0];
    const int*   ei    = (const int*)d_in[1];
    const int*   et    = (const int*)d_in[2];
    const float* W1    = (const float*)d_in[3];
    const float* root1 = (const float*)d_in[4];
    const float* b1    = (const float*)d_in[5];
    const float* W2    = (const float*)d_in[6];
    const float* root2 = (const float*)d_in[7];
    const float* b2    = (const float*)d_in[8];
    float* out = (float*)d_out;

    cudaFuncSetAttribute(gemm_fused<128,0>, cudaFuncAttributeMaxDynamicSharedMemorySize, SMEM1);
    cudaFuncSetAttribute(gemm_fused<96,1>,  cudaFuncAttributeMaxDynamicSharedMemorySize, SMEM2);

    // CSR build (dst-major, relation-sorted within dst)
    zero_cnt_kernel<<<(N_NODES * N_REL + 255) / 256, 256>>>();
    count_kernel<<<(N_EDGES + 255) / 256, 256>>>(ei, et);
    scan1_kernel<<<N_SCANBLKS, SCAN_BLK>>>();
    scan2_kernel<<<1, 128>>>();
    scanfix_kernel<<<N_SCANBLKS, SCAN_BLK>>>();
    reorder_kernel<<<(N_EDGES + 255) / 256, 256>>>(ei, et);

    prep_w1<<<(5 * 128 * 128 + 255) / 256, 256>>>(W1, root1);
    prep_w2<<<(5 * 128 * 96 + 255) / 256, 256>>>(W2, root2);

    // layer 1: out1 = RGCN(x)     (pre-relu stored)
    gemm_fused<128,0><<<N_TILES, 512, SMEM1>>>(x, b1, nullptr);
    // layer 2: out  = RGCN(relu(out1))
    gemm_fused<96,1><<<N_TILES, 512, SMEM2>>>(nullptr, b2, out);
}

// round 10
// speedup vs baseline: 1.1340x; 1.1340x over previous
#include <cuda_runtime.h>
#include <cuda_bf16.h>
#include <cstdint>

#define N_NODES 100000
#define N_EDGES 600000
#define D_IN    128
#define D_OUT   96
#define N_REL   4

#define TILE_M    64
#define N_TILES64 1563               // ceil(100000/64)

#define ROW_BYTES 272                // 128 bf16 (256B) + 16B pad -> conflict-free ldmatrix
#define A_IMG_BYTES (TILE_M * ROW_BYTES)   // 17408
#define B1_ROWS 128
#define B2_ROWS 96
#define B1_IMG_BYTES (B1_ROWS * ROW_BYTES) // 34816
#define B2_IMG_BYTES (B2_ROWS * ROW_BYTES) // 26112

#define SCAN_BLK   1024
#define N_SCANBLKS 98                // ceil(100000/1024)

// ---------------- scratch (static device globals; no allocs allowed) --------
__device__ __align__(16) float g_out1[(size_t)N_NODES * D_IN];          // 51.2 MB
__device__ int      g_cnt[N_NODES * N_REL];
__device__ int      g_cursor[N_NODES * N_REL];
__device__ int      g_base[N_NODES];
__device__ int      g_blocksum[N_SCANBLKS];
__device__ int      g_blockoff[N_SCANBLKS];
__device__ uint32_t g_csr[N_EDGES];

// weight images (bf16 hi/lo, padded rows). B2 rows 96 only.
__device__ uint4 g_B1hi[5 * (B1_IMG_BYTES / 16)];
__device__ uint4 g_B1lo[5 * (B1_IMG_BYTES / 16)];
__device__ uint4 g_B2hi[5 * (B2_IMG_BYTES / 16)];
__device__ uint4 g_B2lo[5 * (B2_IMG_BYTES / 16)];

// ---------------- helpers ----------------------------------------------------
__device__ __forceinline__ uint32_t smem_u32(const void* p) {
    uint32_t a;
    asm("{ .reg .u64 t; cvta.to.shared.u64 t, %1; cvt.u32.u64 %0, t; }" : "=r"(a) : "l"(p));
    return a;
}

#define LDSM4(r, addr)                                                        \
    asm volatile("ldmatrix.sync.aligned.m8n8.x4.shared.b16 {%0,%1,%2,%3}, [%4];" \
                 : "=r"((r)[0]), "=r"((r)[1]), "=r"((r)[2]), "=r"((r)[3])     \
                 : "r"(addr))

#define MMA16816(d, a, b0, b1)                                                \
    asm volatile("mma.sync.aligned.m16n8k16.row.col.f32.bf16.bf16.f32 "       \
                 "{%0,%1,%2,%3},{%4,%5,%6,%7},{%8,%9},{%0,%1,%2,%3};"         \
                 : "+f"((d)[0]), "+f"((d)[1]), "+f"((d)[2]), "+f"((d)[3])     \
                 : "r"((a)[0]), "r"((a)[1]), "r"((a)[2]), "r"((a)[3]),        \
                   "r"(b0), "r"(b1))

__device__ __forceinline__ uint32_t pack_bf16x2(__nv_bfloat16 a, __nv_bfloat16 b) {
    uint32_t r;
    asm("mov.b32 %0, {%1, %2};" : "=r"(r)
        : "h"(*(unsigned short*)&a), "h"(*(unsigned short*)&b));
    return r;
}

__device__ __forceinline__ void split_store8(char* hi_p, char* lo_p, float4 v) {
    __nv_bfloat16 h0 = __float2bfloat16(v.x), h1 = __float2bfloat16(v.y);
    __nv_bfloat16 h2 = __float2bfloat16(v.z), h3 = __float2bfloat16(v.w);
    __nv_bfloat16 l0 = __float2bfloat16(v.x - __bfloat162float(h0));
    __nv_bfloat16 l1 = __float2bfloat16(v.y - __bfloat162float(h1));
    __nv_bfloat16 l2 = __float2bfloat16(v.z - __bfloat162float(h2));
    __nv_bfloat16 l3 = __float2bfloat16(v.w - __bfloat162float(h3));
    *(uint2*)hi_p = make_uint2(pack_bf16x2(h0, h1), pack_bf16x2(h2, h3));
    *(uint2*)lo_p = make_uint2(pack_bf16x2(l0, l1), pack_bf16x2(l2, l3));
}

__device__ __forceinline__ float4 relu4(float4 v) {
    v.x = fmaxf(v.x, 0.f); v.y = fmaxf(v.y, 0.f);
    v.z = fmaxf(v.z, 0.f); v.w = fmaxf(v.w, 0.f);
    return v;
}

// ---------------- CSR build --------------------------------------------------
__global__ void zero_cnt_kernel() {
    int i = blockIdx.x * blockDim.x + threadIdx.x;
    if (i < N_NODES * N_REL) { g_cnt[i] = 0; g_cursor[i] = 0; }
}
__global__ void count_kernel(const int* __restrict__ ei, const int* __restrict__ et) {
    int e = blockIdx.x * blockDim.x + threadIdx.x;
    if (e < N_EDGES) atomicAdd(&g_cnt[ei[N_EDGES + e] * N_REL + et[e]], 1);
}
__global__ void scan1_kernel() {
    __shared__ int s[SCAN_BLK];
    int tid = threadIdx.x;
    int d = blockIdx.x * SCAN_BLK + tid;
    int deg = 0;
    if (d < N_NODES)
        deg = g_cnt[d*4] + g_cnt[d*4+1] + g_cnt[d*4+2] + g_cnt[d*4+3];
    s[tid] = deg;
    __syncthreads();
    for (int off = 1; off < SCAN_BLK; off <<= 1) {
        int v = (tid >= off) ? s[tid - off] : 0;
        __syncthreads();
        s[tid] += v;
        __syncthreads();
    }
    if (d < N_NODES) g_base[d] = s[tid] - deg;
    if (tid == SCAN_BLK - 1) g_blocksum[blockIdx.x] = s[tid];
}
__global__ void scan2_kernel() {
    __shared__ int s[128];
    int tid = threadIdx.x;
    int v = (tid < N_SCANBLKS) ? g_blocksum[tid] : 0;
    s[tid] = v;
    __syncthreads();
    for (int off = 1; off < 128; off <<= 1) {
        int u = (tid >= off) ? s[tid - off] : 0;
        __syncthreads();
        s[tid] += u;
        __syncthreads();
    }
    if (tid < N_SCANBLKS) g_blockoff[tid] = s[tid] - v;
}
__global__ void scanfix_kernel() {
    int d = blockIdx.x * SCAN_BLK + threadIdx.x;
    if (d < N_NODES) g_base[d] += g_blockoff[blockIdx.x];
}
__global__ void reorder_kernel(const int* __restrict__ ei, const int* __restrict__ et) {
    int e = blockIdx.x * blockDim.x + threadIdx.x;
    if (e >= N_EDGES) return;
    int src = ei[e];
    int dst = ei[N_EDGES + e];
    int t   = et[e];
    int pos = atomicAdd(&g_cursor[dst * N_REL + t], 1);
    int sub = 0;
#pragma unroll
    for (int j = 0; j < N_REL - 1; j++) if (j < t) sub += g_cnt[dst * N_REL + j];
    g_csr[g_base[dst] + sub + pos] = (uint32_t)src;
}

// ---------------- weight image prep ------------------------------------------
__global__ void prep_w1(const float* __restrict__ W, const float* __restrict__ root) {
    int e = blockIdx.x * blockDim.x + threadIdx.x;
    if (e >= 5 * 128 * 128) return;
    int batch = e / 16384, r = e % 16384;
    int k = r / 128, n = r % 128;
    float v = (batch < 4) ? W[(size_t)batch * 16384 + k * 128 + n] : root[k * 128 + n];
    __nv_bfloat16 hi = __float2bfloat16(v);
    __nv_bfloat16 lo = __float2bfloat16(v - __bfloat162float(hi));
    size_t off = (size_t)batch * B1_IMG_BYTES + (size_t)n * ROW_BYTES + (size_t)k * 2;
    *(__nv_bfloat16*)((char*)g_B1hi + off) = hi;
    *(__nv_bfloat16*)((char*)g_B1lo + off) = lo;
}
__global__ void prep_w2(const float* __restrict__ W, const float* __restrict__ root) {
    int e = blockIdx.x * blockDim.x + threadIdx.x;
    if (e >= 5 * 128 * 96) return;
    int batch = e / 12288, r = e % 12288;
    int k = r / 96, n = r % 96;
    float v = (batch < 4) ? W[(size_t)batch * 12288 + k * 96 + n] : root[k * 96 + n];
    __nv_bfloat16 hi = __float2bfloat16(v);
    __nv_bfloat16 lo = __float2bfloat16(v - __bfloat162float(hi));
    size_t off = (size_t)batch * B2_IMG_BYTES + (size_t)n * ROW_BYTES + (size_t)k * 2;
    *(__nv_bfloat16*)((char*)g_B2hi + off) = hi;
    *(__nv_bfloat16*)((char*)g_B2lo + off) = lo;
}

// ---------------- fused aggregate+GEMM (64-row tiles, 2 CTAs/SM) -------------
// 256 threads, 8 warps (2 M x 4 N), warp tile 32x32. Warp w stages rows w*8..+7.
// cnt/base preloaded per-lane once; batches use register shfl.
template <int DOUT, int SRC>   // SRC 0: feats = x (ext); 1: feats = relu(g_out1)
__global__ __launch_bounds__(256, 2)
void gemm_fused(const float* __restrict__ xext, const float* __restrict__ bias,
                float* __restrict__ out_ext)
{
    constexpr int B_IMG = (DOUT == 128) ? B1_IMG_BYTES : B2_IMG_BYTES;
    constexpr int B_U4  = B_IMG / 16;
    extern __shared__ char smem[];
    char* sAhi = smem;
    char* sAlo = smem + A_IMG_BYTES;
    char* sBhi = smem + 2 * A_IMG_BYTES;
    char* sBlo = smem + 2 * A_IMG_BYTES + B_IMG;

    int tid = threadIdx.x;
    int wid = tid >> 5, lane = tid & 31;
    int tile = blockIdx.x;

    const float* feats = (SRC == 0) ? xext : g_out1;
    float* Obuf = (DOUT == 128) ? g_out1 : out_ext;

    int warp_m = (wid & 1) * 32;
    int warp_n = (wid >> 1) * 32;
    bool active = (warp_n < DOUT);

    // ---- preload cnt/base for this warp's 8 rows (row = lane&7) ------------
    int my_row = wid * 8 + (lane & 7);
    int my_d   = tile * TILE_M + my_row;
    int4 cw = make_int4(0, 0, 0, 0);
    int  bs = 0;
    if (my_d < N_NODES) {
        cw = *(const int4*)&g_cnt[my_d * 4];
        bs = g_base[my_d];
    }
    // per-lane relation prefix sums (register-only)
    int ps1 = cw.x, ps2 = cw.x + cw.y, ps3 = ps2 + cw.z;

    uint32_t sb = smem_u32(smem);
    uint32_t aoff = (uint32_t)(warp_m + (lane & 15)) * ROW_BYTES + ((lane >> 4) & 1) * 16;
    uint32_t boff = (uint32_t)(warp_n + (lane & 7) + ((lane >> 4) & 1) * 8) * ROW_BYTES
                  + ((lane >> 3) & 1) * 16;

    float acc[2][4][4];
#pragma unroll
    for (int i = 0; i < 2; i++)
#pragma unroll
        for (int j = 0; j < 4; j++)
#pragma unroll
            for (int q = 0; q < 4; q++) acc[i][j][q] = 0.f;

#pragma unroll 1
    for (int batch = 0; batch < 5; batch++) {
        if (batch > 0) __syncthreads();   // prior MMA done reading smem

        // per-lane select for this batch (registers only), then shfl per row
        int c_sel   = (batch == 0) ? cw.x : (batch == 1) ? cw.y
                    : (batch == 2) ? cw.z : cw.w;
        int sub_sel = (batch == 0) ? 0 : (batch == 1) ? ps1
                    : (batch == 2) ? ps2 : ps3;

        // ---- stage A: warp w owns rows w*8..w*8+7 --------------------------
#pragma unroll 1
        for (int i = 0; i < 8; i++) {
            int dl = wid * 8 + i;
            int d  = tile * TILE_M + dl;
            float4 a = make_float4(0.f, 0.f, 0.f, 0.f);
            if (d < N_NODES) {
                if (batch < 4) {
                    int c    = __shfl_sync(0xFFFFFFFFu, c_sel,   i);
                    int sub  = __shfl_sync(0xFFFFFFFFu, sub_sel, i);
                    int base = __shfl_sync(0xFFFFFFFFu, bs,      i);
                    const uint32_t* ep = g_csr + base + sub;
                    float4 a1 = make_float4(0.f,0.f,0.f,0.f);
                    float4 a2 = make_float4(0.f,0.f,0.f,0.f);
                    float4 a3 = make_float4(0.f,0.f,0.f,0.f);
                    int e = 0;
                    for (; e + 3 < c; e += 4) {
                        int s0 = ep[e], s1 = ep[e+1], s2 = ep[e+2], s3 = ep[e+3];
                        float4 v0 = ((const float4*)(feats + (size_t)s0 * 128))[lane];
                        float4 v1 = ((const float4*)(feats + (size_t)s1 * 128))[lane];
                        float4 v2 = ((const float4*)(feats + (size_t)s2 * 128))[lane];
                        float4 v3 = ((const float4*)(feats + (size_t)s3 * 128))[lane];
                        if (SRC == 1) { v0 = relu4(v0); v1 = relu4(v1); v2 = relu4(v2); v3 = relu4(v3); }
                        a.x += v0.x;  a.y += v0.y;  a.z += v0.z;  a.w += v0.w;
                        a1.x += v1.x; a1.y += v1.y; a1.z += v1.z; a1.w += v1.w;
                        a2.x += v2.x; a2.y += v2.y; a2.z += v2.z; a2.w += v2.w;
                        a3.x += v3.x; a3.y += v3.y; a3.z += v3.z; a3.w += v3.w;
                    }
                    for (; e < c; e++) {
                        int s0 = ep[e];
                        float4 v0 = ((const float4*)(feats + (size_t)s0 * 128))[lane];
                        if (SRC == 1) v0 = relu4(v0);
                        a.x += v0.x; a.y += v0.y; a.z += v0.z; a.w += v0.w;
                    }
                    float nm = 1.f / (float)(c > 1 ? c : 1);
                    a.x = (a.x + a1.x + a2.x + a3.x) * nm;
                    a.y = (a.y + a1.y + a2.y + a3.y) * nm;
                    a.z = (a.z + a1.z + a2.z + a3.z) * nm;
                    a.w = (a.w + a1.w + a2.w + a3.w) * nm;
                } else {
                    a = ((const float4*)(feats + (size_t)d * 128))[lane];
                    if (SRC == 1) a = relu4(a);
                }
            }
            split_store8(sAhi + (size_t)dl * ROW_BYTES + lane * 8,
                         sAlo + (size_t)dl * ROW_BYTES + lane * 8, a);
        }

        // ---- stage B (L2-resident weight images) ---------------------------
        {
            const uint4* bhi = (DOUT == 128 ? g_B1hi : g_B2hi) + (size_t)batch * B_U4;
            const uint4* blo = (DOUT == 128 ? g_B1lo : g_B2lo) + (size_t)batch * B_U4;
            uint4* s2 = (uint4*)sBhi;
            uint4* s3 = (uint4*)sBlo;
            for (int i = tid; i < B_U4; i += 256) { s2[i] = bhi[i]; s3[i] = blo[i]; }
        }
        __syncthreads();

        // ---- MMA: accumulate this batch into persistent acc ----------------
        if (active) {
            uint32_t aA[2][2], bA[2][2];
#pragma unroll
            for (int s = 0; s < 2; s++) {
#pragma unroll
                for (int i = 0; i < 2; i++)
                    aA[s][i] = sb + s * A_IMG_BYTES + aoff + i * 16 * ROW_BYTES;
#pragma unroll
                for (int jj = 0; jj < 2; jj++)
                    bA[s][jj] = sb + 2 * A_IMG_BYTES + s * B_IMG + boff + jj * 16 * ROW_BYTES;
            }
#pragma unroll
            for (int kk = 0; kk < 8; kk++) {
                uint32_t ah[2][4], al[2][4], bh[2][4], bl[2][4];
#pragma unroll
                for (int i = 0; i < 2; i++) {
                    LDSM4(ah[i], aA[0][i]);
                    LDSM4(al[i], aA[1][i]);
                    aA[0][i] += 32; aA[1][i] += 32;
                }
#pragma unroll
                for (int jj = 0; jj < 2; jj++) {
                    LDSM4(bh[jj], bA[0][jj]);
                    LDSM4(bl[jj], bA[1][jj]);
                    bA[0][jj] += 32; bA[1][jj] += 32;
                }
#pragma unroll
                for (int i = 0; i < 2; i++) {
#pragma unroll
                    for (int j = 0; j < 4; j++) {
                        int jj = j >> 1, q = (j & 1) * 2;
                        MMA16816(acc[i][j], ah[i], bh[jj][q], bh[jj][q + 1]);
                        MMA16816(acc[i][j], ah[i], bl[jj][q], bl[jj][q + 1]);
                        MMA16816(acc[i][j], al[i], bh[jj][q], bh[jj][q + 1]);
                    }
                }
            }
        }
    }

    // ---- epilogue: complete layer output = agg + root + bias ---------------
    if (active) {
#pragma unroll
        for (int i = 0; i < 2; i++) {
            int row0 = tile * TILE_M + warp_m + i * 16 + (lane >> 2);
#pragma unroll
            for (int j = 0; j < 4; j++) {
                int col = warp_n + j * 8 + (lane & 3) * 2;
                if (col >= DOUT) continue;
                float b0 = bias[col], b1 = bias[col + 1];
                float2 v0 = make_float2(acc[i][j][0] + b0, acc[i][j][1] + b1);
                float2 v1 = make_float2(acc[i][j][2] + b0, acc[i][j][3] + b1);
                if (row0 < N_NODES)
                    *(float2*)(Obuf + (size_t)row0 * DOUT + col) = v0;
                if (row0 + 8 < N_NODES)
                    *(float2*)(Obuf + (size_t)(row0 + 8) * DOUT + col) = v1;
            }
        }
    }
}

// ---------------- launch -----------------------------------------------------
#define SMEM1 (2 * A_IMG_BYTES + 2 * B1_IMG_BYTES)   // 104448 -> 2 CTAs/SM
#define SMEM2 (2 * A_IMG_BYTES + 2 * B2_IMG_BYTES)   // 87040  -> 2 CTAs/SM

extern "C" void kernel_launch(void* const* d_in, const int* in_sizes, int n_in,
                              void* d_out, int out_size)
{
    const float* x     = (const float*)d_in[0];
    const int*   ei    = (const int*)d_in[1];
    const int*   et    = (const int*)d_in[2];
    const float* W1    = (const float*)d_in[3];
    const float* root1 = (const float*)d_in[4];
    const float* b1    = (const float*)d_in[5];
    const float* W2    = (const float*)d_in[6];
    const float* root2 = (const float*)d_in[7];
    const float* b2    = (const float*)d_in[8];
    float* out = (float*)d_out;

    cudaFuncSetAttribute(gemm_fused<128,0>, cudaFuncAttributeMaxDynamicSharedMemorySize, SMEM1);
    cudaFuncSetAttribute(gemm_fused<96,1>,  cudaFuncAttributeMaxDynamicSharedMemorySize, SMEM2);

    // CSR build (dst-major, relation-sorted within dst)
    zero_cnt_kernel<<<(N_NODES * N_REL + 255) / 256, 256>>>();
    count_kernel<<<(N_EDGES + 255) / 256, 256>>>(ei, et);
    scan1_kernel<<<N_SCANBLKS, SCAN_BLK>>>();
    scan2_kernel<<<1, 128>>>();
    scanfix_kernel<<<N_SCANBLKS, SCAN_BLK>>>();
    reorder_kernel<<<(N_EDGES + 255) / 256, 256>>>(ei, et);

    prep_w1<<<(5 * 128 * 128 + 255) / 256, 256>>>(W1, root1);
    prep_w2<<<(5 * 128 * 96 + 255) / 256, 256>>>(W2, root2);

    // layer 1: out1 = RGCN(x)     (pre-relu stored)
    gemm_fused<128,0><<<N_TILES64, 256, SMEM1>>>(x, b1, nullptr);
    // layer 2: out  = RGCN(relu(out1))
    gemm_fused<96,1><<<N_TILES64, 256, SMEM2>>>(nullptr, b2, out);
}

// round 11
// speedup vs baseline: 1.2059x; 1.0634x over previous
#include <cuda_runtime.h>
#include <cuda_bf16.h>
#include <cstdint>

#define N_NODES 100000
#define N_EDGES 600000
#define D_IN    128
#define D_OUT   96
#define N_REL   4

#define TILE_M    64
#define N_TILES64 1563               // ceil(100000/64)

#define ROW_BYTES 272                // 128 bf16 (256B) + 16B pad -> conflict-free ldmatrix
#define A_IMG_BYTES (TILE_M * ROW_BYTES)   // 17408
#define B1_ROWS 128
#define B2_ROWS 96
#define B1_IMG_BYTES (B1_ROWS * ROW_BYTES) // 34816
#define B2_IMG_BYTES (B2_ROWS * ROW_BYTES) // 26112

#define SCAN_BLK   1024
#define N_SCANBLKS 98                // ceil(100000/1024)

// ---------------- scratch (static device globals; no allocs allowed) --------
__device__ __align__(16) float g_out1[(size_t)N_NODES * D_IN];          // 51.2 MB
__device__ int      g_cnt[N_NODES * N_REL];
__device__ int      g_cursor[N_NODES * N_REL];
__device__ int      g_base[N_NODES];
__device__ int      g_blocksum[N_SCANBLKS];
__device__ int      g_blockoff[N_SCANBLKS];
__device__ uint32_t g_csr[N_EDGES];

// weight images (bf16 hi/lo, padded rows). B2 rows 96 only.
__device__ uint4 g_B1hi[5 * (B1_IMG_BYTES / 16)];
__device__ uint4 g_B1lo[5 * (B1_IMG_BYTES / 16)];
__device__ uint4 g_B2hi[5 * (B2_IMG_BYTES / 16)];
__device__ uint4 g_B2lo[5 * (B2_IMG_BYTES / 16)];

// ---------------- helpers ----------------------------------------------------
__device__ __forceinline__ uint32_t smem_u32(const void* p) {
    uint32_t a;
    asm("{ .reg .u64 t; cvta.to.shared.u64 t, %1; cvt.u32.u64 %0, t; }" : "=r"(a) : "l"(p));
    return a;
}

#define LDSM4(r, addr)                                                        \
    asm volatile("ldmatrix.sync.aligned.m8n8.x4.shared.b16 {%0,%1,%2,%3}, [%4];" \
                 : "=r"((r)[0]), "=r"((r)[1]), "=r"((r)[2]), "=r"((r)[3])     \
                 : "r"(addr))

#define MMA16816(d, a, b0, b1)                                                \
    asm volatile("mma.sync.aligned.m16n8k16.row.col.f32.bf16.bf16.f32 "       \
                 "{%0,%1,%2,%3},{%4,%5,%6,%7},{%8,%9},{%0,%1,%2,%3};"         \
                 : "+f"((d)[0]), "+f"((d)[1]), "+f"((d)[2]), "+f"((d)[3])     \
                 : "r"((a)[0]), "r"((a)[1]), "r"((a)[2]), "r"((a)[3]),        \
                   "r"(b0), "r"(b1))

#define CP_ASYNC16(saddr, gptr)                                               \
    asm volatile("cp.async.cg.shared.global [%0], [%1], 16;"                  \
                 :: "r"(saddr), "l"(gptr))
#define CP_COMMIT()  asm volatile("cp.async.commit_group;" ::: "memory")
#define CP_WAIT0()   asm volatile("cp.async.wait_group 0;" ::: "memory")

__device__ __forceinline__ uint32_t pack_bf16x2(__nv_bfloat16 a, __nv_bfloat16 b) {
    uint32_t r;
    asm("mov.b32 %0, {%1, %2};" : "=r"(r)
        : "h"(*(unsigned short*)&a), "h"(*(unsigned short*)&b));
    return r;
}

__device__ __forceinline__ void split_store8(char* hi_p, char* lo_p, float4 v) {
    __nv_bfloat16 h0 = __float2bfloat16(v.x), h1 = __float2bfloat16(v.y);
    __nv_bfloat16 h2 = __float2bfloat16(v.z), h3 = __float2bfloat16(v.w);
    __nv_bfloat16 l0 = __float2bfloat16(v.x - __bfloat162float(h0));
    __nv_bfloat16 l1 = __float2bfloat16(v.y - __bfloat162float(h1));
    __nv_bfloat16 l2 = __float2bfloat16(v.z - __bfloat162float(h2));
    __nv_bfloat16 l3 = __float2bfloat16(v.w - __bfloat162float(h3));
    *(uint2*)hi_p = make_uint2(pack_bf16x2(h0, h1), pack_bf16x2(h2, h3));
    *(uint2*)lo_p = make_uint2(pack_bf16x2(l0, l1), pack_bf16x2(l2, l3));
}

__device__ __forceinline__ float4 relu4(float4 v) {
    v.x = fmaxf(v.x, 0.f); v.y = fmaxf(v.y, 0.f);
    v.z = fmaxf(v.z, 0.f); v.w = fmaxf(v.w, 0.f);
    return v;
}

// ---------------- CSR build --------------------------------------------------
__global__ void zero_cnt_kernel() {
    int i = blockIdx.x * blockDim.x + threadIdx.x;
    if (i < N_NODES * N_REL) { g_cnt[i] = 0; g_cursor[i] = 0; }
}
__global__ void count_kernel(const int* __restrict__ ei, const int* __restrict__ et) {
    int e = blockIdx.x * blockDim.x + threadIdx.x;
    if (e < N_EDGES) atomicAdd(&g_cnt[ei[N_EDGES + e] * N_REL + et[e]], 1);
}
__global__ void scan1_kernel() {
    __shared__ int s[SCAN_BLK];
    int tid = threadIdx.x;
    int d = blockIdx.x * SCAN_BLK + tid;
    int deg = 0;
    if (d < N_NODES)
        deg = g_cnt[d*4] + g_cnt[d*4+1] + g_cnt[d*4+2] + g_cnt[d*4+3];
    s[tid] = deg;
    __syncthreads();
    for (int off = 1; off < SCAN_BLK; off <<= 1) {
        int v = (tid >= off) ? s[tid - off] : 0;
        __syncthreads();
        s[tid] += v;
        __syncthreads();
    }
    if (d < N_NODES) g_base[d] = s[tid] - deg;
    if (tid == SCAN_BLK - 1) g_blocksum[blockIdx.x] = s[tid];
}
__global__ void scan2_kernel() {
    __shared__ int s[128];
    int tid = threadIdx.x;
    int v = (tid < N_SCANBLKS) ? g_blocksum[tid] : 0;
    s[tid] = v;
    __syncthreads();
    for (int off = 1; off < 128; off <<= 1) {
        int u = (tid >= off) ? s[tid - off] : 0;
        __syncthreads();
        s[tid] += u;
        __syncthreads();
    }
    if (tid < N_SCANBLKS) g_blockoff[tid] = s[tid] - v;
}
__global__ void scanfix_kernel() {
    int d = blockIdx.x * SCAN_BLK + threadIdx.x;
    if (d < N_NODES) g_base[d] += g_blockoff[blockIdx.x];
}
__global__ void reorder_kernel(const int* __restrict__ ei, const int* __restrict__ et) {
    int e = blockIdx.x * blockDim.x + threadIdx.x;
    if (e >= N_EDGES) return;
    int src = ei[e];
    int dst = ei[N_EDGES + e];
    int t   = et[e];
    int pos = atomicAdd(&g_cursor[dst * N_REL + t], 1);
    int sub = 0;
#pragma unroll
    for (int j = 0; j < N_REL - 1; j++) if (j < t) sub += g_cnt[dst * N_REL + j];
    g_csr[g_base[dst] + sub + pos] = (uint32_t)src;
}

// ---------------- weight image prep ------------------------------------------
__global__ void prep_w1(const float* __restrict__ W, const float* __restrict__ root) {
    int e = blockIdx.x * blockDim.x + threadIdx.x;
    if (e >= 5 * 128 * 128) return;
    int batch = e / 16384, r = e % 16384;
    int k = r / 128, n = r % 128;
    float v = (batch < 4) ? W[(size_t)batch * 16384 + k * 128 + n] : root[k * 128 + n];
    __nv_bfloat16 hi = __float2bfloat16(v);
    __nv_bfloat16 lo = __float2bfloat16(v - __bfloat162float(hi));
    size_t off = (size_t)batch * B1_IMG_BYTES + (size_t)n * ROW_BYTES + (size_t)k * 2;
    *(__nv_bfloat16*)((char*)g_B1hi + off) = hi;
    *(__nv_bfloat16*)((char*)g_B1lo + off) = lo;
}
__global__ void prep_w2(const float* __restrict__ W, const float* __restrict__ root) {
    int e = blockIdx.x * blockDim.x + threadIdx.x;
    if (e >= 5 * 128 * 96) return;
    int batch = e / 12288, r = e % 12288;
    int k = r / 96, n = r % 96;
    float v = (batch < 4) ? W[(size_t)batch * 12288 + k * 96 + n] : root[k * 96 + n];
    __nv_bfloat16 hi = __float2bfloat16(v);
    __nv_bfloat16 lo = __float2bfloat16(v - __bfloat162float(hi));
    size_t off = (size_t)batch * B2_IMG_BYTES + (size_t)n * ROW_BYTES + (size_t)k * 2;
    *(__nv_bfloat16*)((char*)g_B2hi + off) = hi;
    *(__nv_bfloat16*)((char*)g_B2lo + off) = lo;
}

// ---------------- fused aggregate+GEMM (64-row tiles, 2 CTAs/SM) -------------
// 256 threads, 8 warps (2 M x 4 N), warp tile 32x32. Warp w stages rows w*8..+7.
// Edge lists preloaded lane-parallel into registers (1 LDG/row); B via cp.async.
template <int DOUT, int SRC>   // SRC 0: feats = x (ext); 1: feats = relu(g_out1)
__global__ __launch_bounds__(256, 2)
void gemm_fused(const float* __restrict__ xext, const float* __restrict__ bias,
                float* __restrict__ out_ext)
{
    constexpr int B_IMG = (DOUT == 128) ? B1_IMG_BYTES : B2_IMG_BYTES;
    constexpr int B_U4  = B_IMG / 16;
    extern __shared__ char smem[];
    char* sAhi = smem;
    char* sAlo = smem + A_IMG_BYTES;

    int tid = threadIdx.x;
    int wid = tid >> 5, lane = tid & 31;
    int tile = blockIdx.x;

    const float* feats = (SRC == 0) ? xext : g_out1;
    float* Obuf = (DOUT == 128) ? g_out1 : out_ext;

    int warp_m = (wid & 1) * 32;
    int warp_n = (wid >> 1) * 32;
    bool active = (warp_n < DOUT);

    // ---- preload cnt/base for this warp's 8 rows (row = lane&7) ------------
    int my_row = wid * 8 + (lane & 7);
    int my_d   = tile * TILE_M + my_row;
    int4 cw = make_int4(0, 0, 0, 0);
    int  bs = 0;
    if (my_d < N_NODES) {
        cw = *(const int4*)&g_cnt[my_d * 4];
        bs = g_base[my_d];
    }
    int ps1 = cw.x, ps2 = cw.x + cw.y, ps3 = ps2 + cw.z;
    int deg_total = ps3 + cw.w;

    // ---- preload edge lists: lane-parallel, one LDG per row (MLP-8) --------
    uint32_t eidx[8];
#pragma unroll
    for (int i = 0; i < 8; i++) {
        int base = __shfl_sync(0xFFFFFFFFu, bs, i);
        int deg  = __shfl_sync(0xFFFFFFFFu, deg_total, i);
        eidx[i] = (lane < deg) ? g_csr[base + lane] : 0u;
    }

    uint32_t sb = smem_u32(smem);
    uint32_t aoff = (uint32_t)(warp_m + (lane & 15)) * ROW_BYTES + ((lane >> 4) & 1) * 16;
    uint32_t boff = (uint32_t)(warp_n + (lane & 7) + ((lane >> 4) & 1) * 8) * ROW_BYTES
                  + ((lane >> 3) & 1) * 16;
    uint32_t sBhi_base = sb + 2 * A_IMG_BYTES;
    uint32_t sBlo_base = sb + 2 * A_IMG_BYTES + B_IMG;

    float acc[2][4][4];
#pragma unroll
    for (int i = 0; i < 2; i++)
#pragma unroll
        for (int j = 0; j < 4; j++)
#pragma unroll
            for (int q = 0; q < 4; q++) acc[i][j][q] = 0.f;

#pragma unroll 1
    for (int batch = 0; batch < 5; batch++) {
        if (batch > 0) __syncthreads();   // prior MMA done reading smem

        // ---- B stage via cp.async: hides under the gather below ------------
        {
            const uint4* bhi = (DOUT == 128 ? g_B1hi : g_B2hi) + (size_t)batch * B_U4;
            const uint4* blo = (DOUT == 128 ? g_B1lo : g_B2lo) + (size_t)batch * B_U4;
            for (int i = tid; i < B_U4; i += 256) {
                CP_ASYNC16(sBhi_base + i * 16, bhi + i);
                CP_ASYNC16(sBlo_base + i * 16, blo + i);
            }
            CP_COMMIT();
        }

        int c_sel   = (batch == 0) ? cw.x : (batch == 1) ? cw.y
                    : (batch == 2) ? cw.z : cw.w;
        int sub_sel = (batch == 0) ? 0 : (batch == 1) ? ps1
                    : (batch == 2) ? ps2 : ps3;

        // ---- stage A: warp w owns rows w*8..w*8+7 --------------------------
#pragma unroll 1
        for (int i = 0; i < 8; i++) {
            int dl = wid * 8 + i;
            int d  = tile * TILE_M + dl;
            float4 a = make_float4(0.f, 0.f, 0.f, 0.f);
            if (d < N_NODES) {
                if (batch < 4) {
                    int c   = __shfl_sync(0xFFFFFFFFu, c_sel,   i);
                    int sub = __shfl_sync(0xFFFFFFFFu, sub_sel, i);
                    float4 a1 = make_float4(0.f,0.f,0.f,0.f);
                    if (sub + c <= 32) {
                        // fast path: indices register-resident via shfl
                        int e = 0;
                        for (; e + 1 < c; e += 2) {
                            int s0 = __shfl_sync(0xFFFFFFFFu, eidx[i], sub + e);
                            int s1 = __shfl_sync(0xFFFFFFFFu, eidx[i], sub + e + 1);
                            float4 v0 = ((const float4*)(feats + (size_t)s0 * 128))[lane];
                            float4 v1 = ((const float4*)(feats + (size_t)s1 * 128))[lane];
                            if (SRC == 1) { v0 = relu4(v0); v1 = relu4(v1); }
                            a.x += v0.x;  a.y += v0.y;  a.z += v0.z;  a.w += v0.w;
                            a1.x += v1.x; a1.y += v1.y; a1.z += v1.z; a1.w += v1.w;
                        }
                        if (e < c) {
                            int s0 = __shfl_sync(0xFFFFFFFFu, eidx[i], sub + e);
                            float4 v0 = ((const float4*)(feats + (size_t)s0 * 128))[lane];
                            if (SRC == 1) v0 = relu4(v0);
                            a.x += v0.x; a.y += v0.y; a.z += v0.z; a.w += v0.w;
                        }
                    } else {
                        // rare fallback: memory walk
                        int base = __shfl_sync(0xFFFFFFFFu, bs, i);
                        const uint32_t* ep = g_csr + base + sub;
                        for (int e = 0; e < c; e++) {
                            int s0 = ep[e];
                            float4 v0 = ((const float4*)(feats + (size_t)s0 * 128))[lane];
                            if (SRC == 1) v0 = relu4(v0);
                            a.x += v0.x; a.y += v0.y; a.z += v0.z; a.w += v0.w;
                        }
                    }
                    float nm = 1.f / (float)(c > 1 ? c : 1);
                    a.x = (a.x + a1.x) * nm; a.y = (a.y + a1.y) * nm;
                    a.z = (a.z + a1.z) * nm; a.w = (a.w + a1.w) * nm;
                } else {
                    a = ((const float4*)(feats + (size_t)d * 128))[lane];
                    if (SRC == 1) a = relu4(a);
                }
            }
            split_store8(sAhi + (size_t)dl * ROW_BYTES + lane * 8,
                         sAlo + (size_t)dl * ROW_BYTES + lane * 8, a);
        }

        CP_WAIT0();
        __syncthreads();

        // ---- MMA: accumulate this batch into persistent acc ----------------
        if (active) {
            uint32_t aA[2][2], bA[2][2];
#pragma unroll
            for (int s = 0; s < 2; s++) {
#pragma unroll
                for (int i = 0; i < 2; i++)
                    aA[s][i] = sb + s * A_IMG_BYTES + aoff + i * 16 * ROW_BYTES;
#pragma unroll
                for (int jj = 0; jj < 2; jj++)
                    bA[s][jj] = sb + 2 * A_IMG_BYTES + s * B_IMG + boff + jj * 16 * ROW_BYTES;
            }
#pragma unroll
            for (int kk = 0; kk < 8; kk++) {
                uint32_t ah[2][4], al[2][4], bh[2][4], bl[2][4];
#pragma unroll
                for (int i = 0; i < 2; i++) {
                    LDSM4(ah[i], aA[0][i]);
                    LDSM4(al[i], aA[1][i]);
                    aA[0][i] += 32; aA[1][i] += 32;
                }
#pragma unroll
                for (int jj = 0; jj < 2; jj++) {
                    LDSM4(bh[jj], bA[0][jj]);
                    LDSM4(bl[jj], bA[1][jj]);
                    bA[0][jj] += 32; bA[1][jj] += 32;
                }
#pragma unroll
                for (int i = 0; i < 2; i++) {
#pragma unroll
                    for (int j = 0; j < 4; j++) {
                        int jj = j >> 1, q = (j & 1) * 2;
                        MMA16816(acc[i][j], ah[i], bh[jj][q], bh[jj][q + 1]);
                        MMA16816(acc[i][j], ah[i], bl[jj][q], bl[jj][q + 1]);
                        MMA16816(acc[i][j], al[i], bh[jj][q], bh[jj][q + 1]);
                    }
                }
            }
        }
    }

    // ---- epilogue: complete layer output = agg + root + bias ---------------
    if (active) {
#pragma unroll
        for (int i = 0; i < 2; i++) {
            int row0 = tile * TILE_M + warp_m + i * 16 + (lane >> 2);
#pragma unroll
            for (int j = 0; j < 4; j++) {
                int col = warp_n + j * 8 + (lane & 3) * 2;
                if (col >= DOUT) continue;
                float b0 = bias[col], b1 = bias[col + 1];
                float2 v0 = make_float2(acc[i][j][0] + b0, acc[i][j][1] + b1);
                float2 v1 = make_float2(acc[i][j][2] + b0, acc[i][j][3] + b1);
                if (row0 < N_NODES)
                    *(float2*)(Obuf + (size_t)row0 * DOUT + col) = v0;
                if (row0 + 8 < N_NODES)
                    *(float2*)(Obuf + (size_t)(row0 + 8) * DOUT + col) = v1;
            }
        }
    }
}

// ---------------- launch -----------------------------------------------------
#define SMEM1 (2 * A_IMG_BYTES + 2 * B1_IMG_BYTES)   // 104448 -> 2 CTAs/SM
#define SMEM2 (2 * A_IMG_BYTES + 2 * B2_IMG_BYTES)   // 87040  -> 2 CTAs/SM

extern "C" void kernel_launch(void* const* d_in, const int* in_sizes, int n_in,
                              void* d_out, int out_size)
{
    const float* x     = (const float*)d_in[0];
    const int*   ei    = (const int*)d_in[1];
    const int*   et    = (const int*)d_in[2];
    const float* W1    = (const float*)d_in[3];
    const float* root1 = (const float*)d_in[4];
    const float* b1    = (const float*)d_in[5];
    const float* W2    = (const float*)d_in[6];
    const float* root2 = (const float*)d_in[7];
    const float* b2    = (const float*)d_in[8];
    float* out = (float*)d_out;

    cudaFuncSetAttribute(gemm_fused<128,0>, cudaFuncAttributeMaxDynamicSharedMemorySize, SMEM1);
    cudaFuncSetAttribute(gemm_fused<96,1>,  cudaFuncAttributeMaxDynamicSharedMemorySize, SMEM2);

    // CSR build (dst-major, relation-sorted within dst)
    zero_cnt_kernel<<<(N_NODES * N_REL + 255) / 256, 256>>>();
    count_kernel<<<(N_EDGES + 255) / 256, 256>>>(ei, et);
    scan1_kernel<<<N_SCANBLKS, SCAN_BLK>>>();
    scan2_kernel<<<1, 128>>>();
    scanfix_kernel<<<N_SCANBLKS, SCAN_BLK>>>();
    reorder_kernel<<<(N_EDGES + 255) / 256, 256>>>(ei, et);

    prep_w1<<<(5 * 128 * 128 + 255) / 256, 256>>>(W1, root1);
    prep_w2<<<(5 * 128 * 96 + 255) / 256, 256>>>(W2, root2);

    // layer 1: out1 = RGCN(x)     (pre-relu stored)
    gemm_fused<128,0><<<N_TILES64, 256, SMEM1>>>(x, b1, nullptr);
    // layer 2: out  = RGCN(relu(out1))
    gemm_fused<96,1><<<N_TILES64, 256, SMEM2>>>(nullptr, b2, out);
}